// round 1
// baseline (speedup 1.0000x reference)
#include <cuda_runtime.h>
#include <mma.h>
#include <math.h>

using namespace nvcuda;

// Problem constants (fixed shapes)
#define BATCH 8
#define TLEN  4096
#define H     1024
#define S     16
#define MROWS (BATCH*TLEN)   // 32768

// ---------------- scratch (static device globals; no allocation) ----------------
__device__ float g_xp[33554432];   // [MROWS][H] projected input
__device__ float g_u [33554432];   // [MROWS][H] tanh(...) intermediate
__device__ float g_bx[BATCH*S*TLEN];  // [B*S][T]
__device__ float g_ig[BATCH*S*TLEN];
__device__ float g_fg[BATCH*S*TLEN];
__device__ float g_hs[BATCH*S*TLEN];
__device__ float g_wg[H*64];       // [H][64]: cols 0-15 = W_B@B_mat, 16-31 = W_ig, 32-47 = W_fg, 48-63 = 0
__device__ float g_bg[64];

// ---------------- prep: fold W_B @ B_mat (kills a full HxH GEMM) ----------------
__global__ void prep_w_kernel(const float* __restrict__ WB, const float* __restrict__ Bm,
                              const float* __restrict__ Wig, const float* __restrict__ Wfg) {
    __shared__ float red[128];
    int k = blockIdx.x;           // 0..1023
    int tid = threadIdx.x;        // 128 threads
    int s = tid & 15, p = tid >> 4;
    float acc = 0.f;
    int h0 = p * 128;
    for (int h = h0; h < h0 + 128; ++h)
        acc += WB[k*H + h] * Bm[h*S + s];
    red[tid] = acc;
    __syncthreads();
    if (tid < 16) {
        float sum = 0.f;
        #pragma unroll
        for (int q = 0; q < 8; ++q) sum += red[q*16 + s];
        g_wg[k*64 + s]        = sum;
        g_wg[k*64 + 16 + s]   = Wig[k*S + s];
        g_wg[k*64 + 32 + s]   = Wfg[k*S + s];
        g_wg[k*64 + 48 + s]   = 0.f;
    }
}

__global__ void prep_bias_kernel(const float* __restrict__ bB, const float* __restrict__ Bm,
                                 const float* __restrict__ big, const float* __restrict__ bfg) {
    int tid = threadIdx.x;        // 64 threads
    if (tid < 16) {
        float s = 0.f;
        for (int h = 0; h < H; ++h) s += bB[h] * Bm[h*S + tid];
        g_bg[tid] = s;
    } else if (tid < 32) g_bg[tid] = big[tid-16];
    else if (tid < 48)   g_bg[tid] = bfg[tid-32];
    else                 g_bg[tid] = 0.f;
}

// ---------------- big GEMM: C[M,1024] = A[M,1024] @ W[1024,1024]  (3xTF32, raw acc) ----------------
#define BM 128
#define BN 128
#define BK 32

__global__ void __launch_bounds__(256) gemm3_kernel(const float* __restrict__ A,
                                                    const float* __restrict__ W,
                                                    float* __restrict__ C) {
    __shared__ __align__(16) float As[BM][BK+4];   // row-major, ld=36 (144B rows, 16B aligned)
    __shared__ __align__(16) float Bs[BK][BN+4];   // row-major, ld=132 (528B rows, 16B aligned)

    int bm = blockIdx.y, bn = blockIdx.x;
    int tid = threadIdx.x;
    int wid = tid >> 5;
    int wm = wid >> 2;        // 0..1 : 64 rows each
    int wn = wid & 3;         // 0..3 : 32 cols each

    wmma::fragment<wmma::accumulator, 16, 16, 8, float> c[4][2];
    #pragma unroll
    for (int mi = 0; mi < 4; ++mi)
        #pragma unroll
        for (int ni = 0; ni < 2; ++ni)
            wmma::fill_fragment(c[mi][ni], 0.0f);

    const float* Ab = A + (size_t)bm * BM * H;
    const float* Bb = W + bn * BN;

    for (int kt = 0; kt < H; kt += BK) {
        // load A tile 128x32 (1024 float4 / 256 threads = 4 each)
        #pragma unroll
        for (int j = 0; j < 4; ++j) {
            int idx = tid + 256*j;
            int r = idx >> 3, c4 = idx & 7;
            float4 v = *(const float4*)&Ab[(size_t)r*H + kt + c4*4];
            *(float4*)&As[r][c4*4] = v;
        }
        // load B tile 32x128
        #pragma unroll
        for (int j = 0; j < 4; ++j) {
            int idx = tid + 256*j;
            int r = idx >> 5, c4 = idx & 31;
            *(float4*)&Bs[r][c4*4] = *(const float4*)&Bb[(size_t)(kt + r)*H + c4*4];
        }
        __syncthreads();

        #pragma unroll
        for (int kk = 0; kk < BK; kk += 8) {
            wmma::fragment<wmma::matrix_a, 16, 16, 8, wmma::precision::tf32, wmma::row_major> ah[4], al[4];
            wmma::fragment<wmma::matrix_b, 16, 16, 8, wmma::precision::tf32, wmma::row_major> bh[2], bl[2];
            #pragma unroll
            for (int mi = 0; mi < 4; ++mi) {
                wmma::load_matrix_sync(ah[mi], &As[wm*64 + mi*16][kk], BK+4);
                #pragma unroll
                for (int e = 0; e < ah[mi].num_elements; ++e) {
                    float v = ah[mi].x[e];
                    float hi = wmma::__float_to_tf32(v);
                    al[mi].x[e] = wmma::__float_to_tf32(v - hi);
                    ah[mi].x[e] = hi;
                }
            }
            #pragma unroll
            for (int ni = 0; ni < 2; ++ni) {
                wmma::load_matrix_sync(bh[ni], &Bs[kk][wn*32 + ni*16], BN+4);
                #pragma unroll
                for (int e = 0; e < bh[ni].num_elements; ++e) {
                    float v = bh[ni].x[e];
                    float hi = wmma::__float_to_tf32(v);
                    bl[ni].x[e] = wmma::__float_to_tf32(v - hi);
                    bh[ni].x[e] = hi;
                }
            }
            #pragma unroll
            for (int mi = 0; mi < 4; ++mi)
                #pragma unroll
                for (int ni = 0; ni < 2; ++ni) {
                    wmma::mma_sync(c[mi][ni], ah[mi], bh[ni], c[mi][ni]);
                    wmma::mma_sync(c[mi][ni], al[mi], bh[ni], c[mi][ni]);
                    wmma::mma_sync(c[mi][ni], ah[mi], bl[ni], c[mi][ni]);
                }
        }
        __syncthreads();
    }

    #pragma unroll
    for (int mi = 0; mi < 4; ++mi)
        #pragma unroll
        for (int ni = 0; ni < 2; ++ni) {
            size_t row = (size_t)bm*BM + wm*64 + mi*16;
            size_t col = (size_t)bn*BN + wn*32 + ni*16;
            wmma::store_matrix_sync(&C[row*H + col], c[mi][ni], H, wmma::mem_row_major);
        }
}

// ---------------- elementwise: xp += b_in ----------------
__global__ void ew_bias_kernel(float* __restrict__ buf, const float* __restrict__ bias) {
    int i = blockIdx.x * 256 + threadIdx.x;   // float4 index
    float4 v = ((float4*)buf)[i];
    float4 b = ((const float4*)bias)[i & 255];
    v.x += b.x; v.y += b.y; v.z += b.z; v.w += b.w;
    ((float4*)buf)[i] = v;
}

// ---------------- small fused GEMM: [Bx | ig | fg] = xp @ g_wg (+bias, act), transposed out ----------------
__global__ void __launch_bounds__(256) sgemm_kernel(const float* __restrict__ xp) {
    __shared__ float xs[64][65];
    __shared__ __align__(16) float ws[64][64];
    int row0 = blockIdx.x * 64;
    int b = row0 >> 12;
    int t0 = row0 & (TLEN - 1);
    int tid = threadIdx.x;
    int cg = tid & 15, rg = tid >> 4;
    int c0 = cg * 4, r0 = rg * 4;
    float a[4][4] = {};

    for (int kt = 0; kt < 16; ++kt) {
        #pragma unroll
        for (int j = 0; j < 4; ++j) {
            int idx = tid + 256*j;
            int r = idx >> 4, c4 = idx & 15;
            float4 v = *(const float4*)&xp[(size_t)(row0 + r)*H + kt*64 + c4*4];
            xs[r][c4*4+0] = v.x; xs[r][c4*4+1] = v.y; xs[r][c4*4+2] = v.z; xs[r][c4*4+3] = v.w;
        }
        #pragma unroll
        for (int j = 0; j < 4; ++j) {
            int idx = tid + 256*j;
            int r = idx >> 4, c4 = idx & 15;
            *(float4*)&ws[r][c4*4] = *(const float4*)&g_wg[(kt*64 + r)*64 + c4*4];
        }
        __syncthreads();
        #pragma unroll 8
        for (int k = 0; k < 64; ++k) {
            float4 w = *(float4*)&ws[k][c0];
            float x0 = xs[r0+0][k], x1 = xs[r0+1][k], x2 = xs[r0+2][k], x3 = xs[r0+3][k];
            a[0][0] += x0*w.x; a[0][1] += x0*w.y; a[0][2] += x0*w.z; a[0][3] += x0*w.w;
            a[1][0] += x1*w.x; a[1][1] += x1*w.y; a[1][2] += x1*w.z; a[1][3] += x1*w.w;
            a[2][0] += x2*w.x; a[2][1] += x2*w.y; a[2][2] += x2*w.z; a[2][3] += x2*w.w;
            a[3][0] += x3*w.x; a[3][1] += x3*w.y; a[3][2] += x3*w.z; a[3][3] += x3*w.w;
        }
        __syncthreads();
    }

    #pragma unroll
    for (int rr = 0; rr < 4; ++rr) {
        int t = t0 + r0 + rr;
        #pragma unroll
        for (int j = 0; j < 4; ++j) {
            int cc = c0 + j;
            float v = a[rr][j] + g_bg[cc];
            if (cc < 16)       g_bx[(b*S + cc)      *TLEN + t] = v;
            else if (cc < 32)  g_ig[(b*S + (cc-16)) *TLEN + t] = 1.f/(1.f + expf(-v));
            else if (cc < 48)  g_fg[(b*S + (cc-32)) *TLEN + t] = 1.f/(1.f + expf(-v));
        }
    }
}

// ---------------- parallel linear scan: h_t = fg_t*h_{t-1} + ig_t*bx_t ----------------
__global__ void __launch_bounds__(256) scan_kernel() {
    __shared__ float sA[256], sB[256];
    int ch = blockIdx.x;                       // 0..127 = b*S+s
    const float* fgp = g_fg + (size_t)ch * TLEN;
    const float* igp = g_ig + (size_t)ch * TLEN;
    const float* bxp = g_bx + (size_t)ch * TLEN;
    float* hsp = g_hs + (size_t)ch * TLEN;
    int tid = threadIdx.x;
    int t0 = tid * 16;

    float f[16], gb[16];
    #pragma unroll
    for (int j = 0; j < 4; ++j) {
        float4 fv = *(const float4*)&fgp[t0 + j*4];
        float4 iv = *(const float4*)&igp[t0 + j*4];
        float4 bv = *(const float4*)&bxp[t0 + j*4];
        f[j*4+0] = fv.x; f[j*4+1] = fv.y; f[j*4+2] = fv.z; f[j*4+3] = fv.w;
        gb[j*4+0] = iv.x*bv.x; gb[j*4+1] = iv.y*bv.y; gb[j*4+2] = iv.z*bv.z; gb[j*4+3] = iv.w*bv.w;
    }
    // local composition over 16 elements: h_out = A*h_in + Bv
    float Aa = 1.f, Bv = 0.f;
    #pragma unroll
    for (int i = 0; i < 16; ++i) { Bv = f[i]*Bv + gb[i]; Aa *= f[i]; }
    sA[tid] = Aa; sB[tid] = Bv;
    __syncthreads();
    // Hillis-Steele inclusive scan of (A,B) pairs
    #pragma unroll
    for (int d = 1; d < 256; d <<= 1) {
        float pA = 1.f, pB = 0.f;
        if (tid >= d) { pA = sA[tid-d]; pB = sB[tid-d]; }
        __syncthreads();
        if (tid >= d) {
            float ac = sA[tid], bc = sB[tid];
            sA[tid] = ac * pA;
            sB[tid] = ac * pB + bc;
        }
        __syncthreads();
    }
    float h = (tid > 0) ? sB[tid-1] : 0.f;     // h entering this segment (h0 = 0)
    float o[16];
    #pragma unroll
    for (int i = 0; i < 16; ++i) { h = f[i]*h + gb[i]; o[i] = h; }
    #pragma unroll
    for (int j = 0; j < 4; ++j)
        *(float4*)&hsp[t0 + j*4] = make_float4(o[j*4], o[j*4+1], o[j*4+2], o[j*4+3]);
}

// ---------------- u = tanh(acc + b_D + hs @ C_mat) in place ----------------
__global__ void ew_u_kernel(float* __restrict__ u, const float* __restrict__ bD,
                            const float* __restrict__ Cm) {
    int i = blockIdx.x * 256 + threadIdx.x;    // float4 index
    int col4 = i & 255;
    int row  = i >> 8;
    int b = row >> 12;
    int t = row & (TLEN - 1);
    float4 v  = ((float4*)u)[i];
    float4 bb = ((const float4*)bD)[col4];
    float hx = 0.f, hy = 0.f, hz = 0.f, hw = 0.f;
    #pragma unroll
    for (int s = 0; s < 16; ++s) {
        float hv = g_hs[(b*S + s)*TLEN + t];   // broadcast within warp
        float4 cc = ((const float4*)Cm)[s*256 + col4];
        hx += hv*cc.x; hy += hv*cc.y; hz += hv*cc.z; hw += hv*cc.w;
    }
    v.x = tanhf(v.x + bb.x + hx);
    v.y = tanhf(v.y + bb.y + hy);
    v.z = tanhf(v.z + bb.z + hz);
    v.w = tanhf(v.w + bb.w + hw);
    ((float4*)u)[i] = v;
}

// ---------------- epilogue: y = acc + b_out + xp, then LayerNorm over row ----------------
__global__ void __launch_bounds__(256) ln_kernel(float* __restrict__ out, const float* __restrict__ xp,
                                                 const float* __restrict__ bo, const float* __restrict__ gam,
                                                 const float* __restrict__ bet) {
    __shared__ float rs[8], rq[8];
    int r = blockIdx.x, tid = threadIdx.x;
    float4* o4 = (float4*)(out + (size_t)r * H);
    const float4* x4 = (const float4*)(xp + (size_t)r * H);
    float4 v  = o4[tid];
    float4 bb = ((const float4*)bo)[tid];
    float4 xv = x4[tid];
    float4 y;
    y.x = v.x + bb.x + xv.x;
    y.y = v.y + bb.y + xv.y;
    y.z = v.z + bb.z + xv.z;
    y.w = v.w + bb.w + xv.w;
    float s = y.x + y.y + y.z + y.w;
    float q = y.x*y.x + y.y*y.y + y.z*y.z + y.w*y.w;
    #pragma unroll
    for (int o = 16; o; o >>= 1) {
        s += __shfl_xor_sync(0xFFFFFFFFu, s, o);
        q += __shfl_xor_sync(0xFFFFFFFFu, q, o);
    }
    if ((tid & 31) == 0) { rs[tid >> 5] = s; rq[tid >> 5] = q; }
    __syncthreads();
    if (tid < 32) {
        float s2 = (tid < 8) ? rs[tid] : 0.f;
        float q2 = (tid < 8) ? rq[tid] : 0.f;
        #pragma unroll
        for (int o = 4; o; o >>= 1) {
            s2 += __shfl_xor_sync(0xFFFFFFFFu, s2, o);
            q2 += __shfl_xor_sync(0xFFFFFFFFu, q2, o);
        }
        if (tid == 0) { rs[0] = s2; rq[0] = q2; }
    }
    __syncthreads();
    float mu  = rs[0] * (1.f / 1024.f);
    float var = rq[0] * (1.f / 1024.f) - mu * mu;
    float inv = rsqrtf(var + 1e-5f);
    float4 g = ((const float4*)gam)[tid];
    float4 be = ((const float4*)bet)[tid];
    y.x = (y.x - mu) * inv * g.x + be.x;
    y.y = (y.y - mu) * inv * g.y + be.y;
    y.z = (y.z - mu) * inv * g.z + be.z;
    y.w = (y.w - mu) * inv * g.w + be.w;
    o4[tid] = y;
}

// ---------------- launch ----------------
extern "C" void kernel_launch(void* const* d_in, const int* in_sizes, int n_in,
                              void* d_out, int out_size) {
    const float* x     = (const float*)d_in[0];
    const float* W_in  = (const float*)d_in[1];
    const float* b_in  = (const float*)d_in[2];
    const float* B_mat = (const float*)d_in[3];
    const float* C_mat = (const float*)d_in[4];
    const float* W_B   = (const float*)d_in[5];
    const float* b_B   = (const float*)d_in[6];
    const float* W_D   = (const float*)d_in[7];
    const float* b_D   = (const float*)d_in[8];
    const float* W_out = (const float*)d_in[9];
    const float* b_out = (const float*)d_in[10];
    const float* W_ig  = (const float*)d_in[11];
    const float* b_ig  = (const float*)d_in[12];
    const float* W_fg  = (const float*)d_in[13];
    const float* b_fg  = (const float*)d_in[14];
    const float* gamma = (const float*)d_in[15];
    const float* beta  = (const float*)d_in[16];
    float* out = (float*)d_out;

    float *xp, *u;
    cudaGetSymbolAddress((void**)&xp, g_xp);
    cudaGetSymbolAddress((void**)&u,  g_u);

    const int NF4 = MROWS * H / 4 / 256;   // 32768 blocks of 256 threads, 1 float4 each

    prep_w_kernel<<<H, 128>>>(W_B, B_mat, W_ig, W_fg);
    prep_bias_kernel<<<1, 64>>>(b_B, B_mat, b_ig, b_fg);

    // xp = x @ W_in + b_in
    gemm3_kernel<<<dim3(H/BN, MROWS/BM), 256>>>(x, W_in, xp);
    ew_bias_kernel<<<NF4, 256>>>(xp, b_in);

    // Bx / ig / fg (transposed [B,S,T]) from fused small GEMM
    sgemm_kernel<<<MROWS/64, 256>>>(xp);

    // parallel scan -> hs
    scan_kernel<<<BATCH*S, 256>>>();

    // u = tanh(xp @ W_D + b_D + hs @ C_mat)
    gemm3_kernel<<<dim3(H/BN, MROWS/BM), 256>>>(xp, W_D, u);
    ew_u_kernel<<<NF4, 256>>>(u, b_D, C_mat);

    // out_raw = u @ W_out ; then y = out_raw + b_out + xp ; LayerNorm
    gemm3_kernel<<<dim3(H/BN, MROWS/BM), 256>>>(u, W_out, out);
    ln_kernel<<<MROWS, 256>>>(out, xp, b_out, gamma, beta);
}

// round 4
// speedup vs baseline: 3.1604x; 3.1604x over previous
#include <cuda_runtime.h>
#include <cuda_bf16.h>
#include <cstdint>
#include <math.h>

// Problem constants (fixed shapes)
#define BATCH 8
#define TLEN  4096
#define H     1024
#define S     16
#define MROWS (BATCH*TLEN)   // 32768

// ---------------- scratch (static device globals; no allocation) ----------------
__device__ float g_xp[33554432];                 // [MROWS][H] fp32 (sgemm + residual)
__device__ float g_u [33554432];                 // [MROWS][H] fp32 (pre-tanh)
__device__ __nv_bfloat16 g_xh [33554432], g_xl [33554432];   // x split
__device__ __nv_bfloat16 g_xph[33554432], g_xpl[33554432];   // xp split
__device__ __nv_bfloat16 g_uh [33554432], g_ul [33554432];   // u split
__device__ __nv_bfloat16 g_wth[3*1048576], g_wtl[3*1048576]; // W^T splits [n][k]
__device__ float g_bx[BATCH*S*TLEN];
__device__ float g_ig[BATCH*S*TLEN];
__device__ float g_fg[BATCH*S*TLEN];
__device__ float g_hs[BATCH*S*TLEN];
__device__ float g_wg[H*64];
__device__ float g_bg[64];

// ---------------- PTX helpers (all base sm_100 legal: sm_80-era) ----------------
__device__ __forceinline__ uint32_t smem_u32(const void* p) {
    uint32_t a;
    asm("{ .reg .u64 t; cvta.to.shared.u64 t, %1; cvt.u32.u64 %0, t; }" : "=r"(a) : "l"(p));
    return a;
}
#define CP16(dst, src) \
    asm volatile("cp.async.cg.shared.global [%0], [%1], 16;" :: "r"(dst), "l"(src))
#define CP_COMMIT() asm volatile("cp.async.commit_group;")
#define CP_WAIT(n)  asm volatile("cp.async.wait_group %0;" :: "n"(n))

#define LDSM_X4(r, a) \
    asm volatile("ldmatrix.sync.aligned.m8n8.x4.shared.b16 {%0,%1,%2,%3}, [%4];" \
        : "=r"((r)[0]), "=r"((r)[1]), "=r"((r)[2]), "=r"((r)[3]) : "r"(a))

#define MMA_BF16(c, a, b0, b1) \
    asm volatile("mma.sync.aligned.m16n8k16.row.col.f32.bf16.bf16.f32 " \
        "{%0,%1,%2,%3}, {%4,%5,%6,%7}, {%8,%9}, {%0,%1,%2,%3};" \
        : "+f"((c)[0]), "+f"((c)[1]), "+f"((c)[2]), "+f"((c)[3]) \
        : "r"((a)[0]), "r"((a)[1]), "r"((a)[2]), "r"((a)[3]), "r"(b0), "r"(b1))

// ---------------- bf16-split GEMM: C[M,1024] = A[M,1024] @ W[1024,1024] (+bias) ----------------
// A given as hi/lo bf16 [M][K]; W given transposed hi/lo bf16 [N][K].
// Tile 128(M) x 256(N) x 64(K); 8 warps of 64x64; 2-stage cp.async pipeline.
// Rows stored in SMEM padded to 144B (72 bf16) -> conflict-free ldmatrix.
#define ROWB   144
#define A_SEG  18432            // 128*144
#define B_SEG  36864            // 256*144
#define STG    110592           // Ah + Al + Bh + Bl = 2*A_SEG + 2*B_SEG
#define GEMM_SMEM (2*STG)       // 221184

struct GemmPtrs {
    const __nv_bfloat16 *Ah, *Al, *Bh, *Bl;
};

__device__ __forceinline__ void load_stage(const GemmPtrs& P, int bm, int bn,
                                           int kt, uint32_t sdst, int tid) {
    // A: 2 segs x 128 rows x 8 chunks = 2048 chunks; 8 per thread
    #pragma unroll
    for (int i = 0; i < 8; ++i) {
        int idx = i * 256 + tid;
        int which = idx >> 10;            // 0 hi, 1 lo
        int r = (idx >> 3) & 127;
        int c = idx & 7;
        const __nv_bfloat16* src = (which ? P.Al : P.Ah)
            + (size_t)(bm * 128 + r) * H + kt * 64 + c * 8;
        CP16(sdst + which * A_SEG + r * ROWB + c * 16, src);
    }
    // B: 2 segs x 256 rows x 8 chunks = 4096 chunks; 16 per thread
    #pragma unroll
    for (int i = 0; i < 16; ++i) {
        int idx = i * 256 + tid;
        int which = idx >> 11;
        int r = (idx >> 3) & 255;
        int c = idx & 7;
        const __nv_bfloat16* src = (which ? P.Bl : P.Bh)
            + (size_t)(bn * 256 + r) * H + kt * 64 + c * 8;
        CP16(sdst + 2 * A_SEG + which * B_SEG + r * ROWB + c * 16, src);
    }
    CP_COMMIT();
}

__global__ void __launch_bounds__(256, 1) gemm_bf16(
    const __nv_bfloat16* __restrict__ Ah, const __nv_bfloat16* __restrict__ Al,
    const __nv_bfloat16* __restrict__ Bh, const __nv_bfloat16* __restrict__ Bl,
    float* __restrict__ C, const float* __restrict__ bias,
    __nv_bfloat16* __restrict__ Chi, __nv_bfloat16* __restrict__ Clo)
{
    extern __shared__ char smraw[];
    uint32_t sbase = smem_u32(smraw);
    const int tid = threadIdx.x, lane = tid & 31, wid = tid >> 5;
    const int wm = wid >> 2, wn = wid & 3;          // warp tile 64x64 in 128x256
    const int bn = blockIdx.x, bm = blockIdx.y;
    GemmPtrs P{Ah, Al, Bh, Bl};

    float acc[4][8][4];
    #pragma unroll
    for (int a = 0; a < 4; ++a)
        #pragma unroll
        for (int b = 0; b < 8; ++b)
            #pragma unroll
            for (int c = 0; c < 4; ++c) acc[a][b][c] = 0.f;

    load_stage(P, bm, bn, 0, sbase, tid);

    const int lr = lane & 15, lc = lane >> 4;
    #pragma unroll 1
    for (int kt = 0; kt < 16; ++kt) {
        int s = kt & 1;
        if (kt < 15) { load_stage(P, bm, bn, kt + 1, sbase + (s ^ 1) * STG, tid); CP_WAIT(1); }
        else         { CP_WAIT(0); }
        __syncthreads();

        uint32_t sa = sbase + s * STG;
        uint32_t a_base = sa + (wm * 64 + lr) * ROWB + lc * 16;
        uint32_t b_base = sa + 2 * A_SEG + (wn * 64 + lr) * ROWB + lc * 16;
        #pragma unroll
        for (int k16 = 0; k16 < 4; ++k16) {
            uint32_t ka = a_base + k16 * 32;
            uint32_t kb = b_base + k16 * 32;
            uint32_t ahr[4][4], alr[4][4], bhr[4][4], blr[4][4];
            #pragma unroll
            for (int mf = 0; mf < 4; ++mf) {
                LDSM_X4(ahr[mf], ka + mf * 16 * ROWB);
                LDSM_X4(alr[mf], ka + A_SEG + mf * 16 * ROWB);
            }
            #pragma unroll
            for (int g = 0; g < 4; ++g) {
                LDSM_X4(bhr[g], kb + g * 16 * ROWB);
                LDSM_X4(blr[g], kb + B_SEG + g * 16 * ROWB);
            }
            // x4 on B yields regs {tile0.b0, tile1.b0, tile0.b1, tile1.b1}
            #pragma unroll
            for (int mf = 0; mf < 4; ++mf)
                #pragma unroll
                for (int nf = 0; nf < 8; ++nf) {
                    int g = nf >> 1, h = nf & 1;
                    MMA_BF16(acc[mf][nf], ahr[mf], bhr[g][h], bhr[g][h + 2]);
                    MMA_BF16(acc[mf][nf], alr[mf], bhr[g][h], bhr[g][h + 2]);
                    MMA_BF16(acc[mf][nf], ahr[mf], blr[g][h], blr[g][h + 2]);
                }
        }
        __syncthreads();
    }

    // ---- epilogue: c0,c1 -> (row lr2, col+0/1); c2,c3 -> row lr2+8 ----
    const int lr2 = lane >> 2;
    const int lc2 = (lane & 3) * 2;
    #pragma unroll
    for (int mf = 0; mf < 4; ++mf) {
        size_t row0 = (size_t)bm * 128 + wm * 64 + mf * 16 + lr2;
        #pragma unroll
        for (int nf = 0; nf < 8; ++nf) {
            int col = bn * 256 + wn * 64 + nf * 8 + lc2;
            float b0 = bias[col], b1 = bias[col + 1];
            float v0 = acc[mf][nf][0] + b0, v1 = acc[mf][nf][1] + b1;
            float v2 = acc[mf][nf][2] + b0, v3 = acc[mf][nf][3] + b1;
            *(float2*)&C[row0 * H + col]       = make_float2(v0, v1);
            *(float2*)&C[(row0 + 8) * H + col] = make_float2(v2, v3);
            if (Chi) {
                __nv_bfloat16 h0 = __float2bfloat16(v0), h1 = __float2bfloat16(v1);
                __nv_bfloat16 h2 = __float2bfloat16(v2), h3 = __float2bfloat16(v3);
                *(__nv_bfloat162*)&Chi[row0 * H + col] =
                    __nv_bfloat162(h0, h1);
                *(__nv_bfloat162*)&Chi[(row0 + 8) * H + col] =
                    __nv_bfloat162(h2, h3);
                *(__nv_bfloat162*)&Clo[row0 * H + col] =
                    __nv_bfloat162(__float2bfloat16(v0 - __bfloat162float(h0)),
                                   __float2bfloat16(v1 - __bfloat162float(h1)));
                *(__nv_bfloat162*)&Clo[(row0 + 8) * H + col] =
                    __nv_bfloat162(__float2bfloat16(v2 - __bfloat162float(h2)),
                                   __float2bfloat16(v3 - __bfloat162float(h3)));
            }
        }
    }
}

// ---------------- W transpose + split: W[k][n] fp32 -> Wt_hi/lo[n][k] bf16 ----------------
__global__ void wsplit_kernel(const float* __restrict__ W,
                              __nv_bfloat16* __restrict__ Wth,
                              __nv_bfloat16* __restrict__ Wtl) {
    __shared__ float tile[32][33];
    int bx = blockIdx.x, by = blockIdx.y;
    int tx = threadIdx.x, ty = threadIdx.y;       // 32 x 8
    #pragma unroll
    for (int j = 0; j < 4; ++j)
        tile[ty + j * 8][tx] = W[(size_t)(by * 32 + ty + j * 8) * H + bx * 32 + tx];
    __syncthreads();
    #pragma unroll
    for (int j = 0; j < 4; ++j) {
        int n = bx * 32 + ty + j * 8;
        int k = by * 32 + tx;
        float v = tile[tx][ty + j * 8];
        __nv_bfloat16 hi = __float2bfloat16(v);
        Wth[(size_t)n * H + k] = hi;
        Wtl[(size_t)n * H + k] = __float2bfloat16(v - __bfloat162float(hi));
    }
}

// ---------------- x split (elementwise) ----------------
__global__ void split_kernel(const float* __restrict__ src,
                             __nv_bfloat16* __restrict__ h, __nv_bfloat16* __restrict__ l) {
    int i = blockIdx.x * 256 + threadIdx.x;       // float4 index
    float4 v = ((const float4*)src)[i];
    __nv_bfloat16 hx = __float2bfloat16(v.x), hy = __float2bfloat16(v.y);
    __nv_bfloat16 hz = __float2bfloat16(v.z), hw = __float2bfloat16(v.w);
    ((__nv_bfloat162*)h)[i * 2]     = __nv_bfloat162(hx, hy);
    ((__nv_bfloat162*)h)[i * 2 + 1] = __nv_bfloat162(hz, hw);
    ((__nv_bfloat162*)l)[i * 2]     = __nv_bfloat162(
        __float2bfloat16(v.x - __bfloat162float(hx)),
        __float2bfloat16(v.y - __bfloat162float(hy)));
    ((__nv_bfloat162*)l)[i * 2 + 1] = __nv_bfloat162(
        __float2bfloat16(v.z - __bfloat162float(hz)),
        __float2bfloat16(v.w - __bfloat162float(hw)));
}

// ---------------- prep: fold W_B @ B_mat ----------------
__global__ void prep_w_kernel(const float* __restrict__ WB, const float* __restrict__ Bm,
                              const float* __restrict__ Wig, const float* __restrict__ Wfg) {
    __shared__ float red[128];
    int k = blockIdx.x;
    int tid = threadIdx.x;
    int s = tid & 15, p = tid >> 4;
    float acc = 0.f;
    int h0 = p * 128;
    for (int h = h0; h < h0 + 128; ++h)
        acc += WB[k*H + h] * Bm[h*S + s];
    red[tid] = acc;
    __syncthreads();
    if (tid < 16) {
        float sum = 0.f;
        #pragma unroll
        for (int q = 0; q < 8; ++q) sum += red[q*16 + s];
        g_wg[k*64 + s]        = sum;
        g_wg[k*64 + 16 + s]   = Wig[k*S + s];
        g_wg[k*64 + 32 + s]   = Wfg[k*S + s];
        g_wg[k*64 + 48 + s]   = 0.f;
    }
}

__global__ void prep_bias_kernel(const float* __restrict__ bB, const float* __restrict__ Bm,
                                 const float* __restrict__ big, const float* __restrict__ bfg) {
    int tid = threadIdx.x;
    if (tid < 16) {
        float s = 0.f;
        for (int h = 0; h < H; ++h) s += bB[h] * Bm[h*S + tid];
        g_bg[tid] = s;
    } else if (tid < 32) g_bg[tid] = big[tid-16];
    else if (tid < 48)   g_bg[tid] = bfg[tid-32];
    else                 g_bg[tid] = 0.f;
}

// ---------------- small fused GEMM: [Bx | ig | fg] = xp @ g_wg, transposed out ----------------
__global__ void __launch_bounds__(256) sgemm_kernel(const float* __restrict__ xp) {
    __shared__ float xs[64][65];
    __shared__ __align__(16) float ws[64][64];
    int row0 = blockIdx.x * 64;
    int b = row0 >> 12;
    int t0 = row0 & (TLEN - 1);
    int tid = threadIdx.x;
    int cg = tid & 15, rg = tid >> 4;
    int c0 = cg * 4, r0 = rg * 4;
    float a[4][4] = {};

    for (int kt = 0; kt < 16; ++kt) {
        #pragma unroll
        for (int j = 0; j < 4; ++j) {
            int idx = tid + 256*j;
            int r = idx >> 4, c4 = idx & 15;
            float4 v = *(const float4*)&xp[(size_t)(row0 + r)*H + kt*64 + c4*4];
            xs[r][c4*4+0] = v.x; xs[r][c4*4+1] = v.y; xs[r][c4*4+2] = v.z; xs[r][c4*4+3] = v.w;
        }
        #pragma unroll
        for (int j = 0; j < 4; ++j) {
            int idx = tid + 256*j;
            int r = idx >> 4, c4 = idx & 15;
            *(float4*)&ws[r][c4*4] = *(const float4*)&g_wg[(kt*64 + r)*64 + c4*4];
        }
        __syncthreads();
        #pragma unroll 8
        for (int k = 0; k < 64; ++k) {
            float4 w = *(float4*)&ws[k][c0];
            float x0 = xs[r0+0][k], x1 = xs[r0+1][k], x2 = xs[r0+2][k], x3 = xs[r0+3][k];
            a[0][0] += x0*w.x; a[0][1] += x0*w.y; a[0][2] += x0*w.z; a[0][3] += x0*w.w;
            a[1][0] += x1*w.x; a[1][1] += x1*w.y; a[1][2] += x1*w.z; a[1][3] += x1*w.w;
            a[2][0] += x2*w.x; a[2][1] += x2*w.y; a[2][2] += x2*w.z; a[2][3] += x2*w.w;
            a[3][0] += x3*w.x; a[3][1] += x3*w.y; a[3][2] += x3*w.z; a[3][3] += x3*w.w;
        }
        __syncthreads();
    }

    #pragma unroll
    for (int rr = 0; rr < 4; ++rr) {
        int t = t0 + r0 + rr;
        #pragma unroll
        for (int j = 0; j < 4; ++j) {
            int cc = c0 + j;
            float v = a[rr][j] + g_bg[cc];
            if (cc < 16)       g_bx[(b*S + cc)      *TLEN + t] = v;
            else if (cc < 32)  g_ig[(b*S + (cc-16)) *TLEN + t] = 1.f/(1.f + expf(-v));
            else if (cc < 48)  g_fg[(b*S + (cc-32)) *TLEN + t] = 1.f/(1.f + expf(-v));
        }
    }
}

// ---------------- parallel linear scan ----------------
__global__ void __launch_bounds__(256) scan_kernel() {
    __shared__ float sA[256], sB[256];
    int ch = blockIdx.x;
    const float* fgp = g_fg + (size_t)ch * TLEN;
    const float* igp = g_ig + (size_t)ch * TLEN;
    const float* bxp = g_bx + (size_t)ch * TLEN;
    float* hsp = g_hs + (size_t)ch * TLEN;
    int tid = threadIdx.x;
    int t0 = tid * 16;

    float f[16], gb[16];
    #pragma unroll
    for (int j = 0; j < 4; ++j) {
        float4 fv = *(const float4*)&fgp[t0 + j*4];
        float4 iv = *(const float4*)&igp[t0 + j*4];
        float4 bv = *(const float4*)&bxp[t0 + j*4];
        f[j*4+0] = fv.x; f[j*4+1] = fv.y; f[j*4+2] = fv.z; f[j*4+3] = fv.w;
        gb[j*4+0] = iv.x*bv.x; gb[j*4+1] = iv.y*bv.y; gb[j*4+2] = iv.z*bv.z; gb[j*4+3] = iv.w*bv.w;
    }
    float Aa = 1.f, Bv = 0.f;
    #pragma unroll
    for (int i = 0; i < 16; ++i) { Bv = f[i]*Bv + gb[i]; Aa *= f[i]; }
    sA[tid] = Aa; sB[tid] = Bv;
    __syncthreads();
    #pragma unroll
    for (int d = 1; d < 256; d <<= 1) {
        float pA = 1.f, pB = 0.f;
        if (tid >= d) { pA = sA[tid-d]; pB = sB[tid-d]; }
        __syncthreads();
        if (tid >= d) {
            float ac = sA[tid], bc = sB[tid];
            sA[tid] = ac * pA;
            sB[tid] = ac * pB + bc;
        }
        __syncthreads();
    }
    float h = (tid > 0) ? sB[tid-1] : 0.f;
    float o[16];
    #pragma unroll
    for (int i = 0; i < 16; ++i) { h = f[i]*h + gb[i]; o[i] = h; }
    #pragma unroll
    for (int j = 0; j < 4; ++j)
        *(float4*)&hsp[t0 + j*4] = make_float4(o[j*4], o[j*4+1], o[j*4+2], o[j*4+3]);
}

// ---------------- u = tanh(u + hs @ C_mat); write bf16 split ----------------
__global__ void ew_u_kernel(const float* __restrict__ u, const float* __restrict__ Cm,
                            __nv_bfloat16* __restrict__ uh, __nv_bfloat16* __restrict__ ul) {
    int i = blockIdx.x * 256 + threadIdx.x;
    int col4 = i & 255;
    int row  = i >> 8;
    int b = row >> 12;
    int t = row & (TLEN - 1);
    float4 v  = ((const float4*)u)[i];
    float hx = 0.f, hy = 0.f, hz = 0.f, hw = 0.f;
    #pragma unroll
    for (int s = 0; s < 16; ++s) {
        float hv = g_hs[(b*S + s)*TLEN + t];
        float4 cc = ((const float4*)Cm)[s*256 + col4];
        hx += hv*cc.x; hy += hv*cc.y; hz += hv*cc.z; hw += hv*cc.w;
    }
    v.x = tanhf(v.x + hx);
    v.y = tanhf(v.y + hy);
    v.z = tanhf(v.z + hz);
    v.w = tanhf(v.w + hw);
    __nv_bfloat16 ax = __float2bfloat16(v.x), ay = __float2bfloat16(v.y);
    __nv_bfloat16 az = __float2bfloat16(v.z), aw = __float2bfloat16(v.w);
    ((__nv_bfloat162*)uh)[i * 2]     = __nv_bfloat162(ax, ay);
    ((__nv_bfloat162*)uh)[i * 2 + 1] = __nv_bfloat162(az, aw);
    ((__nv_bfloat162*)ul)[i * 2]     = __nv_bfloat162(
        __float2bfloat16(v.x - __bfloat162float(ax)),
        __float2bfloat16(v.y - __bfloat162float(ay)));
    ((__nv_bfloat162*)ul)[i * 2 + 1] = __nv_bfloat162(
        __float2bfloat16(v.z - __bfloat162float(az)),
        __float2bfloat16(v.w - __bfloat162float(aw)));
}

// ---------------- epilogue: y = acc(+b_out) + xp, LayerNorm ----------------
__global__ void __launch_bounds__(256) ln_kernel(float* __restrict__ out, const float* __restrict__ xp,
                                                 const float* __restrict__ gam, const float* __restrict__ bet) {
    __shared__ float rs[8], rq[8];
    int r = blockIdx.x, tid = threadIdx.x;
    float4* o4 = (float4*)(out + (size_t)r * H);
    const float4* x4 = (const float4*)(xp + (size_t)r * H);
    float4 v  = o4[tid];
    float4 xv = x4[tid];
    float4 y;
    y.x = v.x + xv.x;
    y.y = v.y + xv.y;
    y.z = v.z + xv.z;
    y.w = v.w + xv.w;
    float s = y.x + y.y + y.z + y.w;
    float q = y.x*y.x + y.y*y.y + y.z*y.z + y.w*y.w;
    #pragma unroll
    for (int o = 16; o; o >>= 1) {
        s += __shfl_xor_sync(0xFFFFFFFFu, s, o);
        q += __shfl_xor_sync(0xFFFFFFFFu, q, o);
    }
    if ((tid & 31) == 0) { rs[tid >> 5] = s; rq[tid >> 5] = q; }
    __syncthreads();
    if (tid < 32) {
        float s2 = (tid < 8) ? rs[tid] : 0.f;
        float q2 = (tid < 8) ? rq[tid] : 0.f;
        #pragma unroll
        for (int o = 4; o; o >>= 1) {
            s2 += __shfl_xor_sync(0xFFFFFFFFu, s2, o);
            q2 += __shfl_xor_sync(0xFFFFFFFFu, q2, o);
        }
        if (tid == 0) { rs[0] = s2; rq[0] = q2; }
    }
    __syncthreads();
    float mu  = rs[0] * (1.f / 1024.f);
    float var = rq[0] * (1.f / 1024.f) - mu * mu;
    float inv = rsqrtf(var + 1e-5f);
    float4 g = ((const float4*)gam)[tid];
    float4 be = ((const float4*)bet)[tid];
    y.x = (y.x - mu) * inv * g.x + be.x;
    y.y = (y.y - mu) * inv * g.y + be.y;
    y.z = (y.z - mu) * inv * g.z + be.z;
    y.w = (y.w - mu) * inv * g.w + be.w;
    o4[tid] = y;
}

// ---------------- launch ----------------
extern "C" void kernel_launch(void* const* d_in, const int* in_sizes, int n_in,
                              void* d_out, int out_size) {
    const float* x     = (const float*)d_in[0];
    const float* W_in  = (const float*)d_in[1];
    const float* b_in  = (const float*)d_in[2];
    const float* B_mat = (const float*)d_in[3];
    const float* C_mat = (const float*)d_in[4];
    const float* W_B   = (const float*)d_in[5];
    const float* b_B   = (const float*)d_in[6];
    const float* W_D   = (const float*)d_in[7];
    const float* b_D   = (const float*)d_in[8];
    const float* W_out = (const float*)d_in[9];
    const float* b_out = (const float*)d_in[10];
    const float* W_ig  = (const float*)d_in[11];
    const float* b_ig  = (const float*)d_in[12];
    const float* W_fg  = (const float*)d_in[13];
    const float* b_fg  = (const float*)d_in[14];
    const float* gamma = (const float*)d_in[15];
    const float* beta  = (const float*)d_in[16];
    float* out = (float*)d_out;

    float *xp, *u;
    __nv_bfloat16 *xh, *xl, *xph, *xpl, *uh, *ul, *wth, *wtl;
    cudaGetSymbolAddress((void**)&xp,  g_xp);
    cudaGetSymbolAddress((void**)&u,   g_u);
    cudaGetSymbolAddress((void**)&xh,  g_xh);
    cudaGetSymbolAddress((void**)&xl,  g_xl);
    cudaGetSymbolAddress((void**)&xph, g_xph);
    cudaGetSymbolAddress((void**)&xpl, g_xpl);
    cudaGetSymbolAddress((void**)&uh,  g_uh);
    cudaGetSymbolAddress((void**)&ul,  g_ul);
    cudaGetSymbolAddress((void**)&wth, g_wth);
    cudaGetSymbolAddress((void**)&wtl, g_wtl);

    cudaFuncSetAttribute(gemm_bf16, cudaFuncAttributeMaxDynamicSharedMemorySize, GEMM_SMEM);

    const int NF4 = MROWS * H / 4 / 256;
    dim3 ggrid(H / 256, MROWS / 128);
    dim3 wgrid(32, 32), wblk(32, 8);

    // prep: weight transpose+split, x split, gate weight folding
    wsplit_kernel<<<wgrid, wblk>>>(W_in,  wth,             wtl);
    wsplit_kernel<<<wgrid, wblk>>>(W_D,   wth + 1048576,   wtl + 1048576);
    wsplit_kernel<<<wgrid, wblk>>>(W_out, wth + 2097152,   wtl + 2097152);
    split_kernel<<<NF4, 256>>>(x, xh, xl);
    prep_w_kernel<<<H, 128>>>(W_B, B_mat, W_ig, W_fg);
    prep_bias_kernel<<<1, 64>>>(b_B, B_mat, b_ig, b_fg);

    // xp = x @ W_in + b_in (fp32 + bf16 split outputs)
    gemm_bf16<<<ggrid, 256, GEMM_SMEM>>>(xh, xl, wth, wtl, xp, b_in, xph, xpl);

    // gates (transposed [B,S,T]) and scan
    sgemm_kernel<<<MROWS/64, 256>>>(xp);
    scan_kernel<<<BATCH*S, 256>>>();

    // u = tanh(xp @ W_D + b_D + hs @ C_mat)  (split written by ew_u)
    gemm_bf16<<<ggrid, 256, GEMM_SMEM>>>(xph, xpl, wth + 1048576, wtl + 1048576,
                                         u, b_D, nullptr, nullptr);
    ew_u_kernel<<<NF4, 256>>>(u, C_mat, uh, ul);

    // out = u @ W_out + b_out ; residual + LayerNorm
    gemm_bf16<<<ggrid, 256, GEMM_SMEM>>>(uh, ul, wth + 2097152, wtl + 2097152,
                                         out, b_out, nullptr, nullptr);
    ln_kernel<<<MROWS, 256>>>(out, xp, gamma, beta);
}